// round 9
// baseline (speedup 1.0000x reference)
#include <cuda_runtime.h>
#include <math.h>

// ---------------------------------------------------------------------------
// DSQGAttention: qkv = x@Wqkv^T + b; offset-gather attention over 44 offsets;
// gate = sigmoid(x@Wgate^T + b); out = (attn*gate)@Wout^T + b
// Shapes: B=1, N=2048, D=1024, H=16, HD=64, O=44
// ---------------------------------------------------------------------------

#define NSEQ   2048
#define DMODEL 1024
#define NHEADS 16
#define HDIM   64
#define NOFF   44

__constant__ int c_off[NOFF] = {
    0, 1, 2, 3, 4, 5, 6, 7, 8, 9, 10, 11, 12, 13, 14, 15, 16,
    17, 18, 19, 20, 21, 22, 23, 24, 25, 26, 27, 28, 29, 30, 31, 32,
    48, 64, 96, 128, 192, 256, 384, 512, 768, 1024, 1536};

// Scratch (static device globals -- no runtime allocation allowed)
__device__ float g_qkv[NSEQ * 3 * DMODEL];   // [n, 3*D]: q | k | v
__device__ float g_gate[NSEQ * DMODEL];      // sigmoid(x Wg^T + bg)
__device__ float g_y[NSEQ * DMODEL];         // attn_flat * gate

// ---------------------------------------------------------------------------
// SGEMM (NT): C[M,N] = A[M,K] @ B[N,K]^T + bias[N], optional sigmoid epilogue.
// 128x128 tile, BK=16, 256 threads, 8x8 per-thread accumulator in split-4
// layout (rows ty*4 and 64+ty*4; cols tx*4 and 64+tx*4) so both shared-memory
// fragment loads are conflict-free LDS.128.
// M,N multiples of 128; K multiple of 16 (holds for all three GEMMs here).
// ---------------------------------------------------------------------------
template <int EPI>  // 0 = bias only, 1 = bias + sigmoid
__global__ __launch_bounds__(256, 2)
void sgemm_nt(const float* __restrict__ A, const float* __restrict__ B,
              const float* __restrict__ bias, float* __restrict__ C,
              int M, int N, int K)
{
    constexpr int BM = 128, BN = 128, BK = 16;
    __shared__ float As[BK][BM];   // As[k][m]
    __shared__ float Bs[BK][BN];   // Bs[k][n]

    const int t  = threadIdx.x;
    const int tx = t & 15;          // 0..15 -> column groups
    const int ty = t >> 4;          // 0..15 -> row groups
    const int m0 = blockIdx.y * BM;
    const int n0 = blockIdx.x * BN;

    const float* Ag = A + (size_t)m0 * K;
    const float* Bg = B + (size_t)n0 * K;

    float acc[8][8];
#pragma unroll
    for (int i = 0; i < 8; i++)
#pragma unroll
        for (int j = 0; j < 8; j++) acc[i][j] = 0.0f;

    for (int k0 = 0; k0 < K; k0 += BK) {
        // Load 128x16 tiles of A and B (2 float4 each per thread), store
        // transposed into shared memory.
#pragma unroll
        for (int i = 0; i < 2; i++) {
            int f   = t + i * 256;          // 0..511
            int row = f >> 2;               // 0..127
            int c4  = (f & 3) << 2;         // 0,4,8,12
            float4 va = *(const float4*)(Ag + (size_t)row * K + k0 + c4);
            As[c4 + 0][row] = va.x;
            As[c4 + 1][row] = va.y;
            As[c4 + 2][row] = va.z;
            As[c4 + 3][row] = va.w;
            float4 vb = *(const float4*)(Bg + (size_t)row * K + k0 + c4);
            Bs[c4 + 0][row] = vb.x;
            Bs[c4 + 1][row] = vb.y;
            Bs[c4 + 2][row] = vb.z;
            Bs[c4 + 3][row] = vb.w;
        }
        __syncthreads();

#pragma unroll
        for (int kk = 0; kk < BK; kk++) {
            float4 a0 = *(const float4*)&As[kk][ty * 4];
            float4 a1 = *(const float4*)&As[kk][64 + ty * 4];
            float4 b0 = *(const float4*)&Bs[kk][tx * 4];
            float4 b1 = *(const float4*)&Bs[kk][64 + tx * 4];
            float a[8] = {a0.x, a0.y, a0.z, a0.w, a1.x, a1.y, a1.z, a1.w};
            float b[8] = {b0.x, b0.y, b0.z, b0.w, b1.x, b1.y, b1.z, b1.w};
#pragma unroll
            for (int i = 0; i < 8; i++)
#pragma unroll
                for (int j = 0; j < 8; j++)
                    acc[i][j] = fmaf(a[i], b[j], acc[i][j]);
        }
        __syncthreads();
    }

    // Epilogue: bias (+ sigmoid), float4 stores.
#pragma unroll
    for (int ih = 0; ih < 2; ih++) {
#pragma unroll
        for (int i = 0; i < 4; i++) {
            int r = m0 + ih * 64 + ty * 4 + i;
#pragma unroll
            for (int jh = 0; jh < 2; jh++) {
                int c = n0 + jh * 64 + tx * 4;
                float4 bv = *(const float4*)(bias + c);
                float4 o;
                o.x = acc[ih * 4 + i][jh * 4 + 0] + bv.x;
                o.y = acc[ih * 4 + i][jh * 4 + 1] + bv.y;
                o.z = acc[ih * 4 + i][jh * 4 + 2] + bv.z;
                o.w = acc[ih * 4 + i][jh * 4 + 3] + bv.w;
                if (EPI == 1) {
                    o.x = 1.0f / (1.0f + __expf(-o.x));
                    o.y = 1.0f / (1.0f + __expf(-o.y));
                    o.z = 1.0f / (1.0f + __expf(-o.z));
                    o.w = 1.0f / (1.0f + __expf(-o.w));
                }
                *(float4*)(C + (size_t)r * N + c) = o;
            }
        }
    }
}

// ---------------------------------------------------------------------------
// Offset attention + gating. One warp per (n, h). Lane l owns dims (2l, 2l+1).
// Scores: warp-cooperative 64-dim dots (butterfly reduce). Softmax over 44
// offsets done in-warp (lane l holds offsets l and l+32). Output fused with
// the precomputed gate and written to g_y (flat [n, h*64+d] layout).
// ---------------------------------------------------------------------------
__global__ __launch_bounds__(256)
void attn_gate_kernel(const float* __restrict__ pos_bias)
{
    __shared__ float s_al[8][NOFF];
    const int w  = threadIdx.x >> 5;
    const int l  = threadIdx.x & 31;
    const int gw = blockIdx.x * 8 + w;
    const int h  = gw & (NHEADS - 1);
    const int n  = gw >> 4;

    const float NEG_INF = __int_as_float(0xff800000);

    const float* qrow = g_qkv + (size_t)n * (3 * DMODEL) + h * HDIM + 2 * l;
    const float2 q    = *(const float2*)qrow;
    const float* kbase = g_qkv + DMODEL + h * HDIM + 2 * l;
    const float* vbase = g_qkv + 2 * DMODEL + h * HDIM + 2 * l;

    // ---- scores ----
#pragma unroll
    for (int o = 0; o < NOFF; o++) {
        int m = n - c_off[o];
        float s;
        if (m >= 0) {
            float2 kv = *(const float2*)(kbase + (size_t)m * (3 * DMODEL));
            float p = q.x * kv.x + q.y * kv.y;
            p += __shfl_xor_sync(0xffffffffu, p, 16);
            p += __shfl_xor_sync(0xffffffffu, p, 8);
            p += __shfl_xor_sync(0xffffffffu, p, 4);
            p += __shfl_xor_sync(0xffffffffu, p, 2);
            p += __shfl_xor_sync(0xffffffffu, p, 1);
            s = p * 0.125f + pos_bias[o * NHEADS + h];  // scale = 64^-0.5
        } else {
            s = NEG_INF;
        }
        if (l == 0) s_al[w][o] = s;
    }
    __syncwarp();

    // ---- softmax over 44 offsets (lane l holds slots l, l+32) ----
    float sa = (l < NOFF) ? s_al[w][l] : NEG_INF;
    float sb = (l + 32 < NOFF) ? s_al[w][l + 32] : NEG_INF;
    float mx = fmaxf(sa, sb);
#pragma unroll
    for (int d = 16; d; d >>= 1)
        mx = fmaxf(mx, __shfl_xor_sync(0xffffffffu, mx, d));
    float ea = (l < NOFF) ? __expf(sa - mx) : 0.0f;       // exp(-inf)=0 masked
    float eb = (l + 32 < NOFF) ? __expf(sb - mx) : 0.0f;
    float sm = ea + eb;
#pragma unroll
    for (int d = 16; d; d >>= 1)
        sm += __shfl_xor_sync(0xffffffffu, sm, d);
    float inv = 1.0f / sm;  // offset 0 always valid -> sm > 0
    if (l < NOFF)       s_al[w][l]      = ea * inv;
    if (l + 32 < NOFF)  s_al[w][l + 32] = eb * inv;
    __syncwarp();

    // ---- weighted V sum ----
    float accx = 0.0f, accy = 0.0f;
#pragma unroll
    for (int o = 0; o < NOFF; o++) {
        int m = n - c_off[o];
        if (m >= 0) {
            float a   = s_al[w][o];
            float2 vv = *(const float2*)(vbase + (size_t)m * (3 * DMODEL));
            accx = fmaf(a, vv.x, accx);
            accy = fmaf(a, vv.y, accy);
        }
    }

    // ---- gate + store ----
    int idx = n * DMODEL + h * HDIM + 2 * l;
    float2 g = *(const float2*)(g_gate + idx);
    float2 outv;
    outv.x = accx * g.x;
    outv.y = accy * g.y;
    *(float2*)(g_y + idx) = outv;
}

// ---------------------------------------------------------------------------
// Launch. Inputs (metadata order): x, Wqkv, bqkv, Wout, bout, Wgate, bgate,
// pos_bias. Output: float32 [1, 2048, 1024].
// ---------------------------------------------------------------------------
extern "C" void kernel_launch(void* const* d_in, const int* in_sizes, int n_in,
                              void* d_out, int out_size)
{
    const float* x     = (const float*)d_in[0];
    const float* Wqkv  = (const float*)d_in[1];
    const float* bqkv  = (const float*)d_in[2];
    const float* Wout  = (const float*)d_in[3];
    const float* bout  = (const float*)d_in[4];
    const float* Wgate = (const float*)d_in[5];
    const float* bgate = (const float*)d_in[6];
    const float* pb    = (const float*)d_in[7];
    float* out = (float*)d_out;

    float *qkv, *gate, *y;
    cudaGetSymbolAddress((void**)&qkv,  g_qkv);
    cudaGetSymbolAddress((void**)&gate, g_gate);
    cudaGetSymbolAddress((void**)&y,    g_y);

    dim3 blk(256);

    // 1) qkv = x @ Wqkv^T + bqkv          (2048 x 3072 x 1024)
    sgemm_nt<0><<<dim3(3 * DMODEL / 128, NSEQ / 128), blk>>>(
        x, Wqkv, bqkv, qkv, NSEQ, 3 * DMODEL, DMODEL);

    // 2) gate = sigmoid(x @ Wgate^T + bgate)   (2048 x 1024 x 1024)
    sgemm_nt<1><<<dim3(DMODEL / 128, NSEQ / 128), blk>>>(
        x, Wgate, bgate, gate, NSEQ, DMODEL, DMODEL);

    // 3) y = attention(qkv) * gate       (one warp per (n,h))
    attn_gate_kernel<<<NSEQ * NHEADS / 8, blk>>>(pb);

    // 4) out = y @ Wout^T + bout         (2048 x 1024 x 1024)
    sgemm_nt<0><<<dim3(DMODEL / 128, NSEQ / 128), blk>>>(
        y, Wout, bout, out, NSEQ, DMODEL, DMODEL);
}

// round 11
// speedup vs baseline: 1.0004x; 1.0004x over previous
#include <cuda_runtime.h>
#include <math.h>

// ---------------------------------------------------------------------------
// DSQGAttention: qkv = x@Wqkv^T + b; offset-gather attention over 44 offsets;
// gate = sigmoid(x@Wgate^T + b); out = (attn*gate)@Wout^T + b
// Shapes: B=1, N=2048, D=1024, H=16, HD=64, O=44
// ---------------------------------------------------------------------------

#define NSEQ   2048
#define DMODEL 1024
#define NHEADS 16
#define HDIM   64
#define NOFF   44

__constant__ int c_off[NOFF] = {
    0, 1, 2, 3, 4, 5, 6, 7, 8, 9, 10, 11, 12, 13, 14, 15, 16,
    17, 18, 19, 20, 21, 22, 23, 24, 25, 26, 27, 28, 29, 30, 31, 32,
    48, 64, 96, 128, 192, 256, 384, 512, 768, 1024, 1536};

// Scratch (static device globals -- no runtime allocation allowed)
__device__ float g_qkv[NSEQ * 3 * DMODEL];   // [n, 3*D]: q | k | v
__device__ float g_gate[NSEQ * DMODEL];      // sigmoid(x Wg^T + bg)
__device__ float g_y[NSEQ * DMODEL];         // attn_flat * gate

// ---------------------------------------------------------------------------
// SGEMM (NT): C[M,N] = A[M,K] @ B[N,K]^T + bias[N], optional sigmoid epilogue.
// 128x128 tile, BK=16, 256 threads, 8x8 per-thread accumulator in split-4
// layout (rows ty*4 and 64+ty*4; cols tx*4 and 64+tx*4) so both shared-memory
// fragment loads are conflict-free LDS.128.
// M,N multiples of 128; K multiple of 16 (holds for all three GEMMs here).
// ---------------------------------------------------------------------------
template <int EPI>  // 0 = bias only, 1 = bias + sigmoid
__global__ __launch_bounds__(256, 2)
void sgemm_nt(const float* __restrict__ A, const float* __restrict__ B,
              const float* __restrict__ bias, float* __restrict__ C,
              int M, int N, int K)
{
    constexpr int BM = 128, BN = 128, BK = 16;
    __shared__ float As[BK][BM];   // As[k][m]
    __shared__ float Bs[BK][BN];   // Bs[k][n]

    const int t  = threadIdx.x;
    const int tx = t & 15;          // 0..15 -> column groups
    const int ty = t >> 4;          // 0..15 -> row groups
    const int m0 = blockIdx.y * BM;
    const int n0 = blockIdx.x * BN;

    const float* Ag = A + (size_t)m0 * K;
    const float* Bg = B + (size_t)n0 * K;

    float acc[8][8];
#pragma unroll
    for (int i = 0; i < 8; i++)
#pragma unroll
        for (int j = 0; j < 8; j++) acc[i][j] = 0.0f;

    for (int k0 = 0; k0 < K; k0 += BK) {
        // Load 128x16 tiles of A and B (2 float4 each per thread), store
        // transposed into shared memory.
#pragma unroll
        for (int i = 0; i < 2; i++) {
            int f   = t + i * 256;          // 0..511
            int row = f >> 2;               // 0..127
            int c4  = (f & 3) << 2;         // 0,4,8,12
            float4 va = *(const float4*)(Ag + (size_t)row * K + k0 + c4);
            As[c4 + 0][row] = va.x;
            As[c4 + 1][row] = va.y;
            As[c4 + 2][row] = va.z;
            As[c4 + 3][row] = va.w;
            float4 vb = *(const float4*)(Bg + (size_t)row * K + k0 + c4);
            Bs[c4 + 0][row] = vb.x;
            Bs[c4 + 1][row] = vb.y;
            Bs[c4 + 2][row] = vb.z;
            Bs[c4 + 3][row] = vb.w;
        }
        __syncthreads();

#pragma unroll
        for (int kk = 0; kk < BK; kk++) {
            float4 a0 = *(const float4*)&As[kk][ty * 4];
            float4 a1 = *(const float4*)&As[kk][64 + ty * 4];
            float4 b0 = *(const float4*)&Bs[kk][tx * 4];
            float4 b1 = *(const float4*)&Bs[kk][64 + tx * 4];
            float a[8] = {a0.x, a0.y, a0.z, a0.w, a1.x, a1.y, a1.z, a1.w};
            float b[8] = {b0.x, b0.y, b0.z, b0.w, b1.x, b1.y, b1.z, b1.w};
#pragma unroll
            for (int i = 0; i < 8; i++)
#pragma unroll
                for (int j = 0; j < 8; j++)
                    acc[i][j] = fmaf(a[i], b[j], acc[i][j]);
        }
        __syncthreads();
    }

    // Epilogue: bias (+ sigmoid), float4 stores.
#pragma unroll
    for (int ih = 0; ih < 2; ih++) {
#pragma unroll
        for (int i = 0; i < 4; i++) {
            int r = m0 + ih * 64 + ty * 4 + i;
#pragma unroll
            for (int jh = 0; jh < 2; jh++) {
                int c = n0 + jh * 64 + tx * 4;
                float4 bv = *(const float4*)(bias + c);
                float4 o;
                o.x = acc[ih * 4 + i][jh * 4 + 0] + bv.x;
                o.y = acc[ih * 4 + i][jh * 4 + 1] + bv.y;
                o.z = acc[ih * 4 + i][jh * 4 + 2] + bv.z;
                o.w = acc[ih * 4 + i][jh * 4 + 3] + bv.w;
                if (EPI == 1) {
                    o.x = 1.0f / (1.0f + __expf(-o.x));
                    o.y = 1.0f / (1.0f + __expf(-o.y));
                    o.z = 1.0f / (1.0f + __expf(-o.z));
                    o.w = 1.0f / (1.0f + __expf(-o.w));
                }
                *(float4*)(C + (size_t)r * N + c) = o;
            }
        }
    }
}

// ---------------------------------------------------------------------------
// Offset attention + gating. One warp per (n, h). Lane l owns dims (2l, 2l+1).
// Scores: warp-cooperative 64-dim dots (butterfly reduce). Softmax over 44
// offsets done in-warp (lane l holds offsets l and l+32). Output fused with
// the precomputed gate and written to g_y (flat [n, h*64+d] layout).
// ---------------------------------------------------------------------------
__global__ __launch_bounds__(256)
void attn_gate_kernel(const float* __restrict__ pos_bias)
{
    __shared__ float s_al[8][NOFF];
    const int w  = threadIdx.x >> 5;
    const int l  = threadIdx.x & 31;
    const int gw = blockIdx.x * 8 + w;
    const int h  = gw & (NHEADS - 1);
    const int n  = gw >> 4;

    const float NEG_INF = __int_as_float(0xff800000);

    const float* qrow = g_qkv + (size_t)n * (3 * DMODEL) + h * HDIM + 2 * l;
    const float2 q    = *(const float2*)qrow;
    const float* kbase = g_qkv + DMODEL + h * HDIM + 2 * l;
    const float* vbase = g_qkv + 2 * DMODEL + h * HDIM + 2 * l;

    // ---- scores ----
#pragma unroll
    for (int o = 0; o < NOFF; o++) {
        int m = n - c_off[o];
        float s;
        if (m >= 0) {
            float2 kv = *(const float2*)(kbase + (size_t)m * (3 * DMODEL));
            float p = q.x * kv.x + q.y * kv.y;
            p += __shfl_xor_sync(0xffffffffu, p, 16);
            p += __shfl_xor_sync(0xffffffffu, p, 8);
            p += __shfl_xor_sync(0xffffffffu, p, 4);
            p += __shfl_xor_sync(0xffffffffu, p, 2);
            p += __shfl_xor_sync(0xffffffffu, p, 1);
            s = p * 0.125f + pos_bias[o * NHEADS + h];  // scale = 64^-0.5
        } else {
            s = NEG_INF;
        }
        if (l == 0) s_al[w][o] = s;
    }
    __syncwarp();

    // ---- softmax over 44 offsets (lane l holds slots l, l+32) ----
    float sa = (l < NOFF) ? s_al[w][l] : NEG_INF;
    float sb = (l + 32 < NOFF) ? s_al[w][l + 32] : NEG_INF;
    float mx = fmaxf(sa, sb);
#pragma unroll
    for (int d = 16; d; d >>= 1)
        mx = fmaxf(mx, __shfl_xor_sync(0xffffffffu, mx, d));
    float ea = (l < NOFF) ? __expf(sa - mx) : 0.0f;       // exp(-inf)=0 masked
    float eb = (l + 32 < NOFF) ? __expf(sb - mx) : 0.0f;
    float sm = ea + eb;
#pragma unroll
    for (int d = 16; d; d >>= 1)
        sm += __shfl_xor_sync(0xffffffffu, sm, d);
    float inv = 1.0f / sm;  // offset 0 always valid -> sm > 0
    if (l < NOFF)       s_al[w][l]      = ea * inv;
    if (l + 32 < NOFF)  s_al[w][l + 32] = eb * inv;
    __syncwarp();

    // ---- weighted V sum ----
    float accx = 0.0f, accy = 0.0f;
#pragma unroll
    for (int o = 0; o < NOFF; o++) {
        int m = n - c_off[o];
        if (m >= 0) {
            float a   = s_al[w][o];
            float2 vv = *(const float2*)(vbase + (size_t)m * (3 * DMODEL));
            accx = fmaf(a, vv.x, accx);
            accy = fmaf(a, vv.y, accy);
        }
    }

    // ---- gate + store ----
    int idx = n * DMODEL + h * HDIM + 2 * l;
    float2 g = *(const float2*)(g_gate + idx);
    float2 outv;
    outv.x = accx * g.x;
    outv.y = accy * g.y;
    *(float2*)(g_y + idx) = outv;
}

// ---------------------------------------------------------------------------
// Launch. Inputs (metadata order): x, Wqkv, bqkv, Wout, bout, Wgate, bgate,
// pos_bias. Output: float32 [1, 2048, 1024].
// ---------------------------------------------------------------------------
extern "C" void kernel_launch(void* const* d_in, const int* in_sizes, int n_in,
                              void* d_out, int out_size)
{
    const float* x     = (const float*)d_in[0];
    const float* Wqkv  = (const float*)d_in[1];
    const float* bqkv  = (const float*)d_in[2];
    const float* Wout  = (const float*)d_in[3];
    const float* bout  = (const float*)d_in[4];
    const float* Wgate = (const float*)d_in[5];
    const float* bgate = (const float*)d_in[6];
    const float* pb    = (const float*)d_in[7];
    float* out = (float*)d_out;

    float *qkv, *gate, *y;
    cudaGetSymbolAddress((void**)&qkv,  g_qkv);
    cudaGetSymbolAddress((void**)&gate, g_gate);
    cudaGetSymbolAddress((void**)&y,    g_y);

    dim3 blk(256);

    // 1) qkv = x @ Wqkv^T + bqkv          (2048 x 3072 x 1024)
    sgemm_nt<0><<<dim3(3 * DMODEL / 128, NSEQ / 128), blk>>>(
        x, Wqkv, bqkv, qkv, NSEQ, 3 * DMODEL, DMODEL);

    // 2) gate = sigmoid(x @ Wgate^T + bgate)   (2048 x 1024 x 1024)
    sgemm_nt<1><<<dim3(DMODEL / 128, NSEQ / 128), blk>>>(
        x, Wgate, bgate, gate, NSEQ, DMODEL, DMODEL);

    // 3) y = attention(qkv) * gate       (one warp per (n,h))
    attn_gate_kernel<<<NSEQ * NHEADS / 8, blk>>>(pb);

    // 4) out = y @ Wout^T + bout         (2048 x 1024 x 1024)
    sgemm_nt<0><<<dim3(DMODEL / 128, NSEQ / 128), blk>>>(
        y, Wout, bout, out, NSEQ, DMODEL, DMODEL);
}

// round 16
// speedup vs baseline: 1.0030x; 1.0026x over previous
#include <cuda_runtime.h>
#include <math.h>

// ---------------------------------------------------------------------------
// DSQGAttention: qkv = x@Wqkv^T + b; offset-gather attention over 44 offsets;
// gate = sigmoid(x@Wgate^T + b); out = (attn*gate)@Wout^T + b
// Shapes: B=1, N=2048, D=1024, H=16, HD=64, O=44
// ---------------------------------------------------------------------------

#define NSEQ   2048
#define DMODEL 1024
#define NHEADS 16
#define HDIM   64
#define NOFF   44

__constant__ int c_off[NOFF] = {
    0, 1, 2, 3, 4, 5, 6, 7, 8, 9, 10, 11, 12, 13, 14, 15, 16,
    17, 18, 19, 20, 21, 22, 23, 24, 25, 26, 27, 28, 29, 30, 31, 32,
    48, 64, 96, 128, 192, 256, 384, 512, 768, 1024, 1536};

// Scratch (static device globals -- no runtime allocation allowed)
__device__ float g_qkv[NSEQ * 3 * DMODEL];   // [n, 3*D]: q | k | v
__device__ float g_gate[NSEQ * DMODEL];      // sigmoid(x Wg^T + bg)
__device__ float g_y[NSEQ * DMODEL];         // attn_flat * gate

// ---------------------------------------------------------------------------
// SGEMM (NT): C[M,N] = A[M,K] @ B[N,K]^T + bias[N], optional sigmoid epilogue.
// 128x128 tile, BK=16, 256 threads, 8x8 per-thread accumulator in split-4
// layout (rows ty*4 and 64+ty*4; cols tx*4 and 64+tx*4) so both shared-memory
// fragment loads are conflict-free LDS.128.
// M,N multiples of 128; K multiple of 16 (holds for all three GEMMs here).
// ---------------------------------------------------------------------------
template <int EPI>  // 0 = bias only, 1 = bias + sigmoid
__global__ __launch_bounds__(256, 2)
void sgemm_nt(const float* __restrict__ A, const float* __restrict__ B,
              const float* __restrict__ bias, float* __restrict__ C,
              int M, int N, int K)
{
    constexpr int BM = 128, BN = 128, BK = 16;
    __shared__ float As[BK][BM];   // As[k][m]
    __shared__ float Bs[BK][BN];   // Bs[k][n]

    const int t  = threadIdx.x;
    const int tx = t & 15;          // 0..15 -> column groups
    const int ty = t >> 4;          // 0..15 -> row groups
    const int m0 = blockIdx.y * BM;
    const int n0 = blockIdx.x * BN;

    const float* Ag = A + (size_t)m0 * K;
    const float* Bg = B + (size_t)n0 * K;

    float acc[8][8];
#pragma unroll
    for (int i = 0; i < 8; i++)
#pragma unroll
        for (int j = 0; j < 8; j++) acc[i][j] = 0.0f;

    for (int k0 = 0; k0 < K; k0 += BK) {
        // Load 128x16 tiles of A and B (2 float4 each per thread), store
        // transposed into shared memory.
#pragma unroll
        for (int i = 0; i < 2; i++) {
            int f   = t + i * 256;          // 0..511
            int row = f >> 2;               // 0..127
            int c4  = (f & 3) << 2;         // 0,4,8,12
            float4 va = *(const float4*)(Ag + (size_t)row * K + k0 + c4);
            As[c4 + 0][row] = va.x;
            As[c4 + 1][row] = va.y;
            As[c4 + 2][row] = va.z;
            As[c4 + 3][row] = va.w;
            float4 vb = *(const float4*)(Bg + (size_t)row * K + k0 + c4);
            Bs[c4 + 0][row] = vb.x;
            Bs[c4 + 1][row] = vb.y;
            Bs[c4 + 2][row] = vb.z;
            Bs[c4 + 3][row] = vb.w;
        }
        __syncthreads();

#pragma unroll
        for (int kk = 0; kk < BK; kk++) {
            float4 a0 = *(const float4*)&As[kk][ty * 4];
            float4 a1 = *(const float4*)&As[kk][64 + ty * 4];
            float4 b0 = *(const float4*)&Bs[kk][tx * 4];
            float4 b1 = *(const float4*)&Bs[kk][64 + tx * 4];
            float a[8] = {a0.x, a0.y, a0.z, a0.w, a1.x, a1.y, a1.z, a1.w};
            float b[8] = {b0.x, b0.y, b0.z, b0.w, b1.x, b1.y, b1.z, b1.w};
#pragma unroll
            for (int i = 0; i < 8; i++)
#pragma unroll
                for (int j = 0; j < 8; j++)
                    acc[i][j] = fmaf(a[i], b[j], acc[i][j]);
        }
        __syncthreads();
    }

    // Epilogue: bias (+ sigmoid), float4 stores.
#pragma unroll
    for (int ih = 0; ih < 2; ih++) {
#pragma unroll
        for (int i = 0; i < 4; i++) {
            int r = m0 + ih * 64 + ty * 4 + i;
#pragma unroll
            for (int jh = 0; jh < 2; jh++) {
                int c = n0 + jh * 64 + tx * 4;
                float4 bv = *(const float4*)(bias + c);
                float4 o;
                o.x = acc[ih * 4 + i][jh * 4 + 0] + bv.x;
                o.y = acc[ih * 4 + i][jh * 4 + 1] + bv.y;
                o.z = acc[ih * 4 + i][jh * 4 + 2] + bv.z;
                o.w = acc[ih * 4 + i][jh * 4 + 3] + bv.w;
                if (EPI == 1) {
                    o.x = 1.0f / (1.0f + __expf(-o.x));
                    o.y = 1.0f / (1.0f + __expf(-o.y));
                    o.z = 1.0f / (1.0f + __expf(-o.z));
                    o.w = 1.0f / (1.0f + __expf(-o.w));
                }
                *(float4*)(C + (size_t)r * N + c) = o;
            }
        }
    }
}

// ---------------------------------------------------------------------------
// Offset attention + gating. One warp per (n, h). Lane l owns dims (2l, 2l+1).
// Scores: warp-cooperative 64-dim dots (butterfly reduce). Softmax over 44
// offsets done in-warp (lane l holds offsets l and l+32). Output fused with
// the precomputed gate and written to g_y (flat [n, h*64+d] layout).
// ---------------------------------------------------------------------------
__global__ __launch_bounds__(256)
void attn_gate_kernel(const float* __restrict__ pos_bias)
{
    __shared__ float s_al[8][NOFF];
    const int w  = threadIdx.x >> 5;
    const int l  = threadIdx.x & 31;
    const int gw = blockIdx.x * 8 + w;
    const int h  = gw & (NHEADS - 1);
    const int n  = gw >> 4;

    const float NEG_INF = __int_as_float(0xff800000);

    const float* qrow = g_qkv + (size_t)n * (3 * DMODEL) + h * HDIM + 2 * l;
    const float2 q    = *(const float2*)qrow;
    const float* kbase = g_qkv + DMODEL + h * HDIM + 2 * l;
    const float* vbase = g_qkv + 2 * DMODEL + h * HDIM + 2 * l;

    // ---- scores ----
#pragma unroll
    for (int o = 0; o < NOFF; o++) {
        int m = n - c_off[o];
        float s;
        if (m >= 0) {
            float2 kv = *(const float2*)(kbase + (size_t)m * (3 * DMODEL));
            float p = q.x * kv.x + q.y * kv.y;
            p += __shfl_xor_sync(0xffffffffu, p, 16);
            p += __shfl_xor_sync(0xffffffffu, p, 8);
            p += __shfl_xor_sync(0xffffffffu, p, 4);
            p += __shfl_xor_sync(0xffffffffu, p, 2);
            p += __shfl_xor_sync(0xffffffffu, p, 1);
            s = p * 0.125f + pos_bias[o * NHEADS + h];  // scale = 64^-0.5
        } else {
            s = NEG_INF;
        }
        if (l == 0) s_al[w][o] = s;
    }
    __syncwarp();

    // ---- softmax over 44 offsets (lane l holds slots l, l+32) ----
    float sa = (l < NOFF) ? s_al[w][l] : NEG_INF;
    float sb = (l + 32 < NOFF) ? s_al[w][l + 32] : NEG_INF;
    float mx = fmaxf(sa, sb);
#pragma unroll
    for (int d = 16; d; d >>= 1)
        mx = fmaxf(mx, __shfl_xor_sync(0xffffffffu, mx, d));
    float ea = (l < NOFF) ? __expf(sa - mx) : 0.0f;       // exp(-inf)=0 masked
    float eb = (l + 32 < NOFF) ? __expf(sb - mx) : 0.0f;
    float sm = ea + eb;
#pragma unroll
    for (int d = 16; d; d >>= 1)
        sm += __shfl_xor_sync(0xffffffffu, sm, d);
    float inv = 1.0f / sm;  // offset 0 always valid -> sm > 0
    if (l < NOFF)       s_al[w][l]      = ea * inv;
    if (l + 32 < NOFF)  s_al[w][l + 32] = eb * inv;
    __syncwarp();

    // ---- weighted V sum ----
    float accx = 0.0f, accy = 0.0f;
#pragma unroll
    for (int o = 0; o < NOFF; o++) {
        int m = n - c_off[o];
        if (m >= 0) {
            float a   = s_al[w][o];
            float2 vv = *(const float2*)(vbase + (size_t)m * (3 * DMODEL));
            accx = fmaf(a, vv.x, accx);
            accy = fmaf(a, vv.y, accy);
        }
    }

    // ---- gate + store ----
    int idx = n * DMODEL + h * HDIM + 2 * l;
    float2 g = *(const float2*)(g_gate + idx);
    float2 outv;
    outv.x = accx * g.x;
    outv.y = accy * g.y;
    *(float2*)(g_y + idx) = outv;
}

// ---------------------------------------------------------------------------
// Launch. Inputs (metadata order): x, Wqkv, bqkv, Wout, bout, Wgate, bgate,
// pos_bias. Output: float32 [1, 2048, 1024].
// ---------------------------------------------------------------------------
extern "C" void kernel_launch(void* const* d_in, const int* in_sizes, int n_in,
                              void* d_out, int out_size)
{
    const float* x     = (const float*)d_in[0];
    const float* Wqkv  = (const float*)d_in[1];
    const float* bqkv  = (const float*)d_in[2];
    const float* Wout  = (const float*)d_in[3];
    const float* bout  = (const float*)d_in[4];
    const float* Wgate = (const float*)d_in[5];
    const float* bgate = (const float*)d_in[6];
    const float* pb    = (const float*)d_in[7];
    float* out = (float*)d_out;

    float *qkv, *gate, *y;
    cudaGetSymbolAddress((void**)&qkv,  g_qkv);
    cudaGetSymbolAddress((void**)&gate, g_gate);
    cudaGetSymbolAddress((void**)&y,    g_y);

    dim3 blk(256);

    // 1) qkv = x @ Wqkv^T + bqkv          (2048 x 3072 x 1024)
    sgemm_nt<0><<<dim3(3 * DMODEL / 128, NSEQ / 128), blk>>>(
        x, Wqkv, bqkv, qkv, NSEQ, 3 * DMODEL, DMODEL);

    // 2) gate = sigmoid(x @ Wgate^T + bgate)   (2048 x 1024 x 1024)
    sgemm_nt<1><<<dim3(DMODEL / 128, NSEQ / 128), blk>>>(
        x, Wgate, bgate, gate, NSEQ, DMODEL, DMODEL);

    // 3) y = attention(qkv) * gate       (one warp per (n,h))
    attn_gate_kernel<<<NSEQ * NHEADS / 8, blk>>>(pb);

    // 4) out = y @ Wout^T + bout         (2048 x 1024 x 1024)
    sgemm_nt<0><<<dim3(DMODEL / 128, NSEQ / 128), blk>>>(
        y, Wout, bout, out, NSEQ, DMODEL, DMODEL);
}